// round 7
// baseline (speedup 1.0000x reference)
#include <cuda_runtime.h>
#include <cstdint>

// CTC loss (scaled forward algorithm, linear domain).
// B=512, T=512, C=256, L=64, S=129, blank = C-1.
// Block = 9 warps: warp 0 = recurrence consumer; warps 1..8 = LDG.128
// streaming producers filling a 12-stage x 4-row smem ring (48KB).
// Producer warp w handles chunks c ≡ w-1 (mod 8); stage = c mod 12.

#define TT 512
#define CC 256
#define BB 512
#define LL 64
#define SS 129
#define EPSF 1e-7f
#define RPC 4                  // rows (timesteps) per stage
#define NSTG 12                // ring stages
#define NCH 128                // chunks covering t = 1 .. 511
#define NPROD 8                // producer warps
#define THREADS ((NPROD + 1) * 32)
#define STAGE_FLOATS (RPC * CC)
#define STAGE_BYTES (STAGE_FLOATS * 4)
#define SMEM_BYTES (NSTG * STAGE_BYTES + 2 * NSTG * 8 + 16)

__device__ __forceinline__ uint32_t smem_u32(const void* p) {
    uint32_t a;
    asm("{ .reg .u64 t; cvta.to.shared.u64 t, %1; cvt.u32.u64 %0, t; }"
        : "=r"(a) : "l"(p));
    return a;
}
__device__ __forceinline__ void mbar_init(uint32_t addr, uint32_t cnt) {
    asm volatile("mbarrier.init.shared.b64 [%0], %1;" :: "r"(addr), "r"(cnt) : "memory");
}
__device__ __forceinline__ void mbar_arrive(uint32_t addr) {
    asm volatile("mbarrier.arrive.release.cta.shared::cta.b64 _, [%0];"
                 :: "r"(addr) : "memory");
}
__device__ __forceinline__ void mbar_wait(uint32_t addr, uint32_t parity) {
    asm volatile(
        "{\n\t.reg .pred P;\n\t"
        "LAB_WAIT_%=:\n\t"
        "mbarrier.try_wait.parity.acquire.cta.shared::cta.b64 P, [%0], %1, 0x989680;\n\t"
        "@P bra.uni LAB_DONE_%=;\n\t"
        "bra.uni LAB_WAIT_%=;\n\t"
        "LAB_DONE_%=:\n\t}"
        :: "r"(addr), "r"(parity) : "memory");
}

__global__ __launch_bounds__(THREADS, 4)
void ctc_ldg_kernel(const int* __restrict__ y_true,
                    const float* __restrict__ y_pred,
                    float* __restrict__ out)
{
    extern __shared__ __align__(16) unsigned char smem_raw[];
    float* sp = (float*)smem_raw;                            // NSTG stages
    unsigned long long* full_s =
        (unsigned long long*)(smem_raw + NSTG * STAGE_BYTES);
    unsigned long long* empty_s = full_s + NSTG;

    const int b    = blockIdx.x;
    const int tid  = threadIdx.x;
    const int wid  = tid >> 5;
    const int lane = tid & 31;
    const unsigned FULL = 0xFFFFFFFFu;

    const float* __restrict__ yp  = y_pred + (size_t)b * TT * CC;
    const int*   __restrict__ lab = y_true + b * LL;

    if (tid == 0) {
#pragma unroll
        for (int s = 0; s < NSTG; s++) {
            mbar_init(smem_u32(&full_s[s]), 32);   // 32 producer-lane arrives
            mbar_init(smem_u32(&empty_s[s]), 32);  // 32 consumer-lane arrives
        }
    }
    __syncthreads();

    if (wid != 0) {
        // ---------------- producer warps ----------------
        const int w = wid - 1;
#pragma unroll 1
        for (int c = w; c < NCH; c += NPROD) {
            const int s = c % NSTG;
            const int j = c / NSTG;
            const uint32_t eadr = smem_u32(&empty_s[s]);
            if (j > 0) mbar_wait(eadr, (j - 1) & 1);

            const int t0 = 1 + RPC * c;
            const int n4 = ((TT - t0 < RPC) ? (TT - t0) : RPC) * (CC / 4);
            const float4* __restrict__ g = (const float4*)(yp + (size_t)t0 * CC);
            float4* st = (float4*)(sp + s * STAGE_FLOATS);

            float4 v[8];
#pragma unroll
            for (int i = 0; i < 8; i++) {
                int idx = lane + 32 * i;
                v[i] = (idx < n4) ? g[idx] : make_float4(0.f, 0.f, 0.f, 0.f);
            }
#pragma unroll
            for (int i = 0; i < 8; i++) {
                int idx = lane + 32 * i;
                if (idx < n4) st[idx] = v[i];
            }
            mbar_arrive(smem_u32(&full_s[s]));
        }
        return;
    }

    // ---------------- consumer warp (warp 0) ----------------
    // static state metadata: s = 32k + lane
    int   off[5];
    float skipf[5];
#pragma unroll
    for (int k = 0; k < 5; k++) {
        int s = 32 * k + lane;
        if (s < SS && (s & 1)) {
            int idx = (s - 1) >> 1;
            int cl  = lab[idx];
            off[k]  = cl;
            skipf[k] = (idx > 0 && cl != lab[idx - 1]) ? 1.0f : 0.0f;
        } else {
            off[k]  = CC - 1;     // blank (safe dummy for invalid s > 128)
            skipf[k] = 0.0f;
        }
    }

    // t = 0 init
    float a[5];
#pragma unroll
    for (int k = 0; k < 5; k++) a[k] = 0.0f;
    if (lane == 0)      a[0] = yp[CC - 1] + EPSF;
    else if (lane == 1) a[0] = yp[lab[0]] + EPSF;

    int E = 0;
    int buf = 0, trip = 0;
    const int lm1 = (lane + 31) & 31;
    const int lm2 = (lane + 30) & 31;

#pragma unroll 1
    for (int c = 0; c < NCH; c++) {
        const int tbase = 1 + RPC * c;
        const float* stage = sp + buf * STAGE_FLOATS;

        mbar_wait(smem_u32(&full_s[buf]), trip);

        // row-0 prob prefetch
        float p[5];
#pragma unroll
        for (int k = 0; k < 5; k++) p[k] = stage[off[k]] + EPSF;

        // one rescale group == one 4-row stage.  max measured at group start
        // (lagged 1 group), butterfly interleaved with the steps; exact pow-2
        // scale applied at group end, target biased to 2^40 (above FTZ).
        float m = fmaxf(fmaxf(fmaxf(a[0], a[1]), fmaxf(a[2], a[3])), a[4]);
        m = fmaxf(m, __shfl_xor_sync(FULL, m, 16));

#pragma unroll
        for (int i = 0; i < 4; i++) {
            int t = tbase + i;
            if (t < TT) {
                bool pf = (i + 1 < RPC) && (t + 1 < TT);
                float np[5];
                const float* rn = stage + (i + 1) * CC;
                if (pf) {
#pragma unroll
                    for (int k = 0; k < 5; k++) np[k] = rn[off[k]] + EPSF;
                }
                float r1[5], r2[5];
#pragma unroll
                for (int k = 0; k < 5; k++) r1[k] = __shfl_sync(FULL, a[k], lm1);
#pragma unroll
                for (int k = 0; k < 5; k++) r2[k] = __shfl_sync(FULL, a[k], lm2);
#pragma unroll
                for (int k = 0; k < 5; k++) {
                    float u1 = r1[k];
                    if (lane == 0) u1 = (k > 0) ? r1[k - 1] : 0.0f;
                    float u2 = r2[k];
                    if (lane < 2)  u2 = (k > 0) ? r2[k - 1] : 0.0f;
                    float sum = a[k] + u1 + skipf[k] * u2;
                    a[k] = sum * p[k];
                    if (pf) p[k] = np[k];
                }
            }
            if (i == 0) m = fmaxf(m, __shfl_xor_sync(FULL, m, 8));
            if (i == 1) m = fmaxf(m, __shfl_xor_sync(FULL, m, 4));
            if (i == 2) m = fmaxf(m, __shfl_xor_sync(FULL, m, 2));
            if (i == 3) m = fmaxf(m, __shfl_xor_sync(FULL, m, 1));
        }
        {
            int e = (__float_as_int(m) >> 23) & 255;
            int f = 294 - e;                    // exponent field of 2^(167-e)
            if (f > 254) f = 254;
            if (f < 1)   f = 1;
            float sc = __int_as_float(f << 23); // exact power of 2
            E -= (f - 127);
#pragma unroll
            for (int k = 0; k < 5; k++) a[k] *= sc;
        }

        // stage drained by this lane -> signal empty (32 arrives flip it)
        mbar_arrive(smem_u32(&empty_s[buf]));

        if (++buf == NSTG) { buf = 0; trip ^= 1; }
    }

    // loss = -log(alpha[S-1] + alpha[S-2]), scale restored
    float v127 = __shfl_sync(FULL, a[3], 31);   // state 127 = 32*3 + 31
    float v128 = __shfl_sync(FULL, a[4], 0);    // state 128 = 32*4 + 0
    if (lane == 0)
        out[b] = -(logf(v127 + v128) + (float)E * 0.69314718055994530942f);
}

extern "C" void kernel_launch(void* const* d_in, const int* in_sizes, int n_in,
                              void* d_out, int out_size)
{
    const int*   y_true;
    const float* y_pred;
    if (in_sizes[0] == BB * LL) {
        y_true = (const int*)d_in[0];
        y_pred = (const float*)d_in[1];
    } else {
        y_true = (const int*)d_in[1];
        y_pred = (const float*)d_in[0];
    }
    float* out = (float*)d_out;

    cudaFuncSetAttribute(ctc_ldg_kernel,
                         cudaFuncAttributeMaxDynamicSharedMemorySize,
                         SMEM_BYTES);
    ctc_ldg_kernel<<<BB, THREADS, SMEM_BYTES>>>(y_true, y_pred, out);
}

// round 8
// speedup vs baseline: 1.8180x; 1.8180x over previous
#include <cuda_runtime.h>
#include <cstdint>

// CTC loss (scaled forward algorithm, linear domain).
// B=512, T=512, C=256, L=64, S=129, blank = C-1.
// One warp per batch, LANE-MAJOR state mapping: s = 5*lane + k (k=0..4).
//   k>=2 : a[s-1], a[s-2] are same-lane registers (no shuffle)
//   k==0 : u1 = lane-1's a[4], u2 = lane-1's a[3]
//   k==1 : u1 = own a[0],      u2 = lane-1's a[4]
// => 2 shuffles per timestep (vs 10 in the k-major layout).
// Probabilities streamed via cp.async.bulk into a 6-stage x 8-row ring (48KB).

#define TT 512
#define CC 256
#define BB 512
#define LL 64
#define SS 129
#define EPSF 1e-7f
#define RPC 8                  // rows (timesteps) per stage
#define NSTG 6                 // ring stages
#define NCH 64                 // chunks covering t = 1 .. 511
#define STAGE_FLOATS (RPC * CC)
#define STAGE_BYTES (STAGE_FLOATS * 4)
#define SMEM_BYTES (NSTG * STAGE_BYTES + NSTG * 8 + 16)

__device__ __forceinline__ uint32_t smem_u32(const void* p) {
    uint32_t a;
    asm("{ .reg .u64 t; cvta.to.shared.u64 t, %1; cvt.u32.u64 %0, t; }"
        : "=r"(a) : "l"(p));
    return a;
}
__device__ __forceinline__ void mbar_init(uint32_t addr, uint32_t cnt) {
    asm volatile("mbarrier.init.shared.b64 [%0], %1;" :: "r"(addr), "r"(cnt) : "memory");
}
__device__ __forceinline__ void mbar_expect_tx(uint32_t addr, uint32_t bytes) {
    asm volatile("mbarrier.arrive.expect_tx.shared.b64 _, [%0], %1;"
                 :: "r"(addr), "r"(bytes) : "memory");
}
__device__ __forceinline__ void mbar_wait(uint32_t addr, uint32_t parity) {
    asm volatile(
        "{\n\t.reg .pred P;\n\t"
        "LAB_WAIT_%=:\n\t"
        "mbarrier.try_wait.parity.acquire.cta.shared::cta.b64 P, [%0], %1, 0x989680;\n\t"
        "@P bra.uni LAB_DONE_%=;\n\t"
        "bra.uni LAB_WAIT_%=;\n\t"
        "LAB_DONE_%=:\n\t}"
        :: "r"(addr), "r"(parity) : "memory");
}
__device__ __forceinline__ void bulk_copy(uint32_t dst, const void* src,
                                          uint32_t bytes, uint32_t mbar) {
    asm volatile(
        "cp.async.bulk.shared::cluster.global.mbarrier::complete_tx::bytes "
        "[%0], [%1], %2, [%3];"
        :: "r"(dst), "l"(src), "r"(bytes), "r"(mbar) : "memory");
}

__global__ __launch_bounds__(32, 4)
void ctc_lm_kernel(const int* __restrict__ y_true,
                   const float* __restrict__ y_pred,
                   float* __restrict__ out)
{
    extern __shared__ __align__(16) unsigned char smem_raw[];
    float* sp = (float*)smem_raw;
    unsigned long long* mbar_s =
        (unsigned long long*)(smem_raw + NSTG * STAGE_BYTES);

    const int b    = blockIdx.x;
    const int lane = threadIdx.x;
    const unsigned FULL = 0xFFFFFFFFu;

    const float* __restrict__ yp  = y_pred + (size_t)b * TT * CC;
    const int*   __restrict__ lab = y_true + b * LL;

    // ---- static per-(lane,k) metadata, lane-major: s = 5*lane + k ----
    int   off[5];
    float skipf[5];
#pragma unroll
    for (int k = 0; k < 5; k++) {
        int s = 5 * lane + k;
        if (s < SS && (s & 1)) {
            int idx = (s - 1) >> 1;
            int cl  = lab[idx];
            off[k]  = cl;
            skipf[k] = (idx > 0 && cl != lab[idx - 1]) ? 1.0f : 0.0f;
        } else {
            off[k]  = CC - 1;     // blank (also safe dummy for invalid s)
            skipf[k] = 0.0f;
        }
    }

    // ---- t = 0 init: states 0 (blank) and 1 (label 0) live on lane 0 ----
    float a[5];
#pragma unroll
    for (int k = 0; k < 5; k++) a[k] = 0.0f;
    if (lane == 0) {
        a[0] = yp[CC - 1]  + EPSF;
        a[1] = yp[lab[0]] + EPSF;
    }

    // ---- prologue: init barriers, launch all NSTG stage fills ----
    if (lane == 0) {
#pragma unroll
        for (int s = 0; s < NSTG; s++) mbar_init(smem_u32(&mbar_s[s]), 1);
        asm volatile("fence.proxy.async.shared::cta;" ::: "memory");
#pragma unroll
        for (int c0 = 0; c0 < NSTG; c0++) {
            int t0   = 1 + RPC * c0;
            int rows = (TT - t0 < RPC) ? (TT - t0) : RPC;
            uint32_t bytes = (uint32_t)rows * CC * 4;
            mbar_expect_tx(smem_u32(&mbar_s[c0]), bytes);
            bulk_copy(smem_u32(sp + c0 * STAGE_FLOATS), yp + (size_t)t0 * CC,
                      bytes, smem_u32(&mbar_s[c0]));
        }
    }
    __syncwarp();

    int E = 0;
    int buf = 0, trip = 0;
    const int lm1 = (lane + 31) & 31;

#pragma unroll 1
    for (int c = 0; c < NCH; c++) {
        const int tbase = 1 + RPC * c;
        const float* stage = sp + buf * STAGE_FLOATS;
        const uint32_t mbadr = smem_u32(&mbar_s[buf]);

        mbar_wait(mbadr, trip);

        // row-0 prob prefetch
        float p[5];
#pragma unroll
        for (int k = 0; k < 5; k++) p[k] = stage[off[k]] + EPSF;

        // 8 steps = 2 rescale groups of 4. Max measured at group start
        // (lagged one group), butterfly interleaved with the steps; exact
        // pow-2 scale applied at group end, target biased to 2^40 (>= FTZ).
#pragma unroll
        for (int g = 0; g < RPC / 4; g++) {
            float m = fmaxf(fmaxf(fmaxf(a[0], a[1]), fmaxf(a[2], a[3])), a[4]);
            m = fmaxf(m, __shfl_xor_sync(FULL, m, 16));

#pragma unroll
            for (int i = 0; i < 4; i++) {
                int j = g * 4 + i;
                int t = tbase + j;
                if (t < TT) {
                    bool pf = (j + 1 < RPC) && (t + 1 < TT);
                    float np[5];
                    const float* rn = stage + (j + 1) * CC;
                    if (pf) {
#pragma unroll
                        for (int k = 0; k < 5; k++) np[k] = rn[off[k]] + EPSF;
                    }
                    // 2 shuffles/step: neighbor's a[4], a[3]
                    float A4 = __shfl_sync(FULL, a[4], lm1);
                    float A3 = __shfl_sync(FULL, a[3], lm1);
                    if (lane == 0) { A4 = 0.0f; A3 = 0.0f; }

                    float s0 = a[0] + A4   + skipf[0] * A3;
                    float s1 = a[1] + a[0] + skipf[1] * A4;
                    float s2 = a[2] + a[1] + skipf[2] * a[0];
                    float s3 = a[3] + a[2] + skipf[3] * a[1];
                    float s4 = a[4] + a[3] + skipf[4] * a[2];
                    a[0] = s0 * p[0];
                    a[1] = s1 * p[1];
                    a[2] = s2 * p[2];
                    a[3] = s3 * p[3];
                    a[4] = s4 * p[4];
                    if (pf) {
#pragma unroll
                        for (int k = 0; k < 5; k++) p[k] = np[k];
                    }
                }
                if (i == 0) m = fmaxf(m, __shfl_xor_sync(FULL, m, 8));
                if (i == 1) m = fmaxf(m, __shfl_xor_sync(FULL, m, 4));
                if (i == 2) m = fmaxf(m, __shfl_xor_sync(FULL, m, 2));
                if (i == 3) m = fmaxf(m, __shfl_xor_sync(FULL, m, 1));
            }
            int e = (__float_as_int(m) >> 23) & 255;
            int f = 294 - e;                    // exponent field of 2^(167-e)
            if (f > 254) f = 254;
            if (f < 1)   f = 1;
            float sc = __int_as_float(f << 23); // exact power of 2
            E -= (f - 127);
#pragma unroll
            for (int k = 0; k < 5; k++) a[k] *= sc;
        }

        // stage drained by all lanes -> refill with chunk c+NSTG
        __syncwarp();
        int cn = c + NSTG;
        if (cn < NCH && lane == 0) {
            int t0   = 1 + RPC * cn;
            int rows = (TT - t0 < RPC) ? (TT - t0) : RPC;
            uint32_t bytes = (uint32_t)rows * CC * 4;
            mbar_expect_tx(mbadr, bytes);
            bulk_copy(smem_u32(sp + buf * STAGE_FLOATS), yp + (size_t)t0 * CC,
                      bytes, mbadr);
        }

        if (++buf == NSTG) { buf = 0; trip ^= 1; }
    }

    // ---- loss: states 127,128 live on lane 25 (k=2, k=3) ----
    float v127 = __shfl_sync(FULL, a[2], 25);
    float v128 = __shfl_sync(FULL, a[3], 25);
    if (lane == 0)
        out[b] = -(logf(v127 + v128) + (float)E * 0.69314718055994530942f);
}

extern "C" void kernel_launch(void* const* d_in, const int* in_sizes, int n_in,
                              void* d_out, int out_size)
{
    const int*   y_true;
    const float* y_pred;
    if (in_sizes[0] == BB * LL) {
        y_true = (const int*)d_in[0];
        y_pred = (const float*)d_in[1];
    } else {
        y_true = (const int*)d_in[1];
        y_pred = (const float*)d_in[0];
    }
    float* out = (float*)d_out;

    cudaFuncSetAttribute(ctc_lm_kernel,
                         cudaFuncAttributeMaxDynamicSharedMemorySize,
                         SMEM_BYTES);
    ctc_lm_kernel<<<BB, 32, SMEM_BYTES>>>(y_true, y_pred, out);
}